// round 5
// baseline (speedup 1.0000x reference)
#include <cuda_runtime.h>

#define NMAX 200000
#define KOFF 27
#define TILE 128
#define TILESMAX ((NMAX + TILE - 1) / TILE)
#define SEGW (TILESMAX + 1)
#define BN_EPS 1e-3f

// ---------------- scratch (__device__ globals; no allocs allowed) ----------
__device__ __align__(256) float g_acc1[(size_t)NMAX * 32];
__device__ __align__(256) float g_x1  [(size_t)NMAX * 32];
__device__ __align__(256) float g_acc2[(size_t)NMAX * 32];
__device__ int   g_seg[KOFF * SEGW];
// [0:64) L1 sum/sumsq  [64:128) L2 sum/sumsq  [128:192) L1 sc/sh  [192:256) L2 sc/sh
__device__ float g_sums[256];

__device__ __forceinline__ unsigned smem_u32(const void* p) {
    return (unsigned)__cvta_generic_to_shared(p);
}
__device__ __forceinline__ void cp_async16(unsigned dst, const void* src) {
    asm volatile("cp.async.cg.shared.global [%0], [%1], 16;\n" :: "r"(dst), "l"(src));
}
#define CP_COMMIT asm volatile("cp.async.commit_group;\n" ::: "memory")
#define CP_WAIT0  asm volatile("cp.async.wait_group 0;\n" ::: "memory")

// ---------------- seg: per (k, dst-tile) pair-range via binary search ------
__global__ void seg_k(const int* __restrict__ rout, int n, int tiles) {
    if (blockIdx.x == 0 && threadIdx.x < 128) g_sums[threadIdx.x] = 0.f;
    int idx = blockIdx.x * blockDim.x + threadIdx.x;
    int total = KOFF * (tiles + 1);
    if (idx >= total) return;
    int k = idx / (tiles + 1), t = idx % (tiles + 1);
    int target = t * TILE;
    if (target > n) target = n;
    const int* a = rout + (size_t)k * n;
    int lo = 0, hi = n;
    while (lo < hi) {
        int mid = (lo + hi) >> 1;
        if (a[mid] < target) lo = mid + 1; else hi = mid;
    }
    g_seg[k * SEGW + t] = lo;
}

// ---------------- conv: tag-gather + register-C accumulation ---------------
// Block owns 128 dst rows; thread owns 4 rows x 4 cols in registers across all
// offsets. Gather (cp.async) writes x[src] into Ash[dst-r0] and stamps
// tag[dst-r0]=k (dst unique per offset => race-free). Compute reads rows only
// where tag==k. No C tile in smem, no global atomics, 1 barrier per offset.
template <int CIN>
__global__ void __launch_bounds__(256) conv_k(
    const float* __restrict__ X, const float* __restrict__ W,
    const int* __restrict__ rin, const int* __restrict__ rout,
    float* __restrict__ out, int n, int statoff)
{
    const int AS  = CIN + 4;               // Ash row stride (floats); 144B/80B = 16B mult
    const int CH  = CIN / 4;               // float4 per feature row
    const int CSH = (CIN == 32) ? 3 : 2;   // log2(CH)
    const int PF  = (128 * CH) / 256;      // gather chunks per thread (4 or 2)

    extern __shared__ float smem[];
    float* AshB = smem;                    // 2 * 128 * AS
    float* WshB = AshB + 2 * 128 * AS;     // 2 * CIN * 32
    float* red  = WshB + 2 * CIN * 32;     // 512
    int*   tagB = (int*)(red + 512);       // 2 * 128
    int*   klist = tagB + 256;             // 27
    int*   klo   = klist + KOFF;           // 27
    int*   kln   = klo + KOFF;             // 27
    int*   sst   = kln + KOFF;             // 27
    int*   sen   = sst + KOFF;             // 27
    int*   nksh  = sen + KOFF;             // 1

    int tx = threadIdx.x;
    int tile = blockIdx.x;
    int r0 = tile * TILE;

    if (tx < KOFF) { sst[tx] = g_seg[tx * SEGW + tile]; sen[tx] = g_seg[tx * SEGW + tile + 1]; }
    tagB[tx] = -1;                         // init both tag buffers (256 ints)
    __syncthreads();
    if (tx == 0) {
        int m = 0;
        for (int k = 0; k < KOFF; k++) {
            int L = sen[k] - sst[k];
            if (L > 0) { klist[m] = k; klo[m] = sst[k]; kln[m] = L; m++; }
        }
        *nksh = m;
    }
    __syncthreads();
    int nk = *nksh;

    // two index-register sets, parity j&1 matches buffer parity
    int psrc[2][PF], pdst[2][PF];

    auto load_idx = [&](int j) {
        int b = j & 1, k = klist[j], s = klo[j], L = kln[j];
        #pragma unroll
        for (int i = 0; i < PF; i++) {
            int gi = tx + i * 256;
            int row = gi >> CSH;
            if (row < L) {
                psrc[b][i] = __ldg(rin + (size_t)k * n + s + row);
                pdst[b][i] = __ldg(rout + (size_t)k * n + s + row) - r0;
            } else pdst[b][i] = -1;
        }
    };

    auto issue_copies = [&](int j) {
        int b = j & 1;
        float* Ash = AshB + b * 128 * AS;
        float* Wsh = WshB + b * CIN * 32;
        int*   tag = tagB + b * 128;
        int k = klist[j];
        if (tx < CIN * 8)
            cp_async16(smem_u32(Wsh + tx * 4), W + (size_t)k * CIN * 32 + tx * 4);
        #pragma unroll
        for (int i = 0; i < PF; i++) {
            int gi = tx + i * 256;
            int co = gi & (CH - 1);
            int d = pdst[b][i];
            if (d >= 0) {
                cp_async16(smem_u32(Ash + d * AS + co * 4),
                           X + (size_t)psrc[b][i] * CIN + co * 4);
                if (co == 0) tag[d] = k;
            }
        }
        CP_COMMIT;
    };

    // prologue
    if (nk > 0) {
        load_idx(0);
        issue_copies(0);
        if (nk > 1) load_idx(1);
        CP_WAIT0;
    }
    __syncthreads();

    const int rg = tx >> 3, cg = tx & 7;
    const int rb = rg * 4;
    float4 acc[4];
    #pragma unroll
    for (int i = 0; i < 4; i++) acc[i] = make_float4(0.f, 0.f, 0.f, 0.f);

    for (int i = 0; i < nk; i++) {
        int buf = i & 1;
        if (i + 1 < nk) issue_copies(i + 1);   // writes buf^1 (sealed last barrier)
        if (i + 2 < nk) load_idx(i + 2);       // idx set (i+2)&1 == buf: regs only

        float* Ash = AshB + buf * 128 * AS;
        float* Wsh = WshB + buf * CIN * 32;
        int*   tag = tagB + buf * 128;
        int k = klist[i];

        bool v0 = (tag[rb + 0] == k), v1 = (tag[rb + 1] == k),
             v2 = (tag[rb + 2] == k), v3 = (tag[rb + 3] == k);

        if (v0 | v1 | v2 | v3) {
            #pragma unroll
            for (int c4 = 0; c4 < CIN / 4; c4++) {
                int ci = c4 * 4;
                float4 z = make_float4(0.f, 0.f, 0.f, 0.f);
                float4 a0 = v0 ? *(const float4*)&Ash[(rb + 0) * AS + ci] : z;
                float4 a1 = v1 ? *(const float4*)&Ash[(rb + 1) * AS + ci] : z;
                float4 a2 = v2 ? *(const float4*)&Ash[(rb + 2) * AS + ci] : z;
                float4 a3 = v3 ? *(const float4*)&Ash[(rb + 3) * AS + ci] : z;
                float4 w0 = *(const float4*)&Wsh[(ci + 0) * 32 + cg * 4];
                float4 w1 = *(const float4*)&Wsh[(ci + 1) * 32 + cg * 4];
                float4 w2 = *(const float4*)&Wsh[(ci + 2) * 32 + cg * 4];
                float4 w3 = *(const float4*)&Wsh[(ci + 3) * 32 + cg * 4];

                acc[0].x = fmaf(a0.x, w0.x, acc[0].x); acc[0].y = fmaf(a0.x, w0.y, acc[0].y);
                acc[0].z = fmaf(a0.x, w0.z, acc[0].z); acc[0].w = fmaf(a0.x, w0.w, acc[0].w);
                acc[1].x = fmaf(a1.x, w0.x, acc[1].x); acc[1].y = fmaf(a1.x, w0.y, acc[1].y);
                acc[1].z = fmaf(a1.x, w0.z, acc[1].z); acc[1].w = fmaf(a1.x, w0.w, acc[1].w);
                acc[2].x = fmaf(a2.x, w0.x, acc[2].x); acc[2].y = fmaf(a2.x, w0.y, acc[2].y);
                acc[2].z = fmaf(a2.x, w0.z, acc[2].z); acc[2].w = fmaf(a2.x, w0.w, acc[2].w);
                acc[3].x = fmaf(a3.x, w0.x, acc[3].x); acc[3].y = fmaf(a3.x, w0.y, acc[3].y);
                acc[3].z = fmaf(a3.x, w0.z, acc[3].z); acc[3].w = fmaf(a3.x, w0.w, acc[3].w);

                acc[0].x = fmaf(a0.y, w1.x, acc[0].x); acc[0].y = fmaf(a0.y, w1.y, acc[0].y);
                acc[0].z = fmaf(a0.y, w1.z, acc[0].z); acc[0].w = fmaf(a0.y, w1.w, acc[0].w);
                acc[1].x = fmaf(a1.y, w1.x, acc[1].x); acc[1].y = fmaf(a1.y, w1.y, acc[1].y);
                acc[1].z = fmaf(a1.y, w1.z, acc[1].z); acc[1].w = fmaf(a1.y, w1.w, acc[1].w);
                acc[2].x = fmaf(a2.y, w1.x, acc[2].x); acc[2].y = fmaf(a2.y, w1.y, acc[2].y);
                acc[2].z = fmaf(a2.y, w1.z, acc[2].z); acc[2].w = fmaf(a2.y, w1.w, acc[2].w);
                acc[3].x = fmaf(a3.y, w1.x, acc[3].x); acc[3].y = fmaf(a3.y, w1.y, acc[3].y);
                acc[3].z = fmaf(a3.y, w1.z, acc[3].z); acc[3].w = fmaf(a3.y, w1.w, acc[3].w);

                acc[0].x = fmaf(a0.z, w2.x, acc[0].x); acc[0].y = fmaf(a0.z, w2.y, acc[0].y);
                acc[0].z = fmaf(a0.z, w2.z, acc[0].z); acc[0].w = fmaf(a0.z, w2.w, acc[0].w);
                acc[1].x = fmaf(a1.z, w2.x, acc[1].x); acc[1].y = fmaf(a1.z, w2.y, acc[1].y);
                acc[1].z = fmaf(a1.z, w2.z, acc[1].z); acc[1].w = fmaf(a1.z, w2.w, acc[1].w);
                acc[2].x = fmaf(a2.z, w2.x, acc[2].x); acc[2].y = fmaf(a2.z, w2.y, acc[2].y);
                acc[2].z = fmaf(a2.z, w2.z, acc[2].z); acc[2].w = fmaf(a2.z, w2.w, acc[2].w);
                acc[3].x = fmaf(a3.z, w2.x, acc[3].x); acc[3].y = fmaf(a3.z, w2.y, acc[3].y);
                acc[3].z = fmaf(a3.z, w2.z, acc[3].z); acc[3].w = fmaf(a3.z, w2.w, acc[3].w);

                acc[0].x = fmaf(a0.w, w3.x, acc[0].x); acc[0].y = fmaf(a0.w, w3.y, acc[0].y);
                acc[0].z = fmaf(a0.w, w3.z, acc[0].z); acc[0].w = fmaf(a0.w, w3.w, acc[0].w);
                acc[1].x = fmaf(a1.w, w3.x, acc[1].x); acc[1].y = fmaf(a1.w, w3.y, acc[1].y);
                acc[1].z = fmaf(a1.w, w3.z, acc[1].z); acc[1].w = fmaf(a1.w, w3.w, acc[1].w);
                acc[2].x = fmaf(a2.w, w3.x, acc[2].x); acc[2].y = fmaf(a2.w, w3.y, acc[2].y);
                acc[2].z = fmaf(a2.w, w3.z, acc[2].z); acc[2].w = fmaf(a2.w, w3.w, acc[2].w);
                acc[3].x = fmaf(a3.w, w3.x, acc[3].x); acc[3].y = fmaf(a3.w, w3.y, acc[3].y);
                acc[3].z = fmaf(a3.w, w3.z, acc[3].z); acc[3].w = fmaf(a3.w, w3.w, acc[3].w);
            }
        }
        CP_WAIT0;
        __syncthreads();
    }

    // epilogue: register C -> global store + warp-shuffle BN stats
    int nrows = n - r0; if (nrows > TILE) nrows = TILE;
    float4 s = make_float4(0.f, 0.f, 0.f, 0.f);
    float4 q = make_float4(0.f, 0.f, 0.f, 0.f);
    #pragma unroll
    for (int i = 0; i < 4; i++) {
        int row = rb + i;
        if (row < nrows) {
            *(float4*)(out + (size_t)(r0 + row) * 32 + cg * 4) = acc[i];
            s.x += acc[i].x; s.y += acc[i].y; s.z += acc[i].z; s.w += acc[i].w;
            q.x = fmaf(acc[i].x, acc[i].x, q.x); q.y = fmaf(acc[i].y, acc[i].y, q.y);
            q.z = fmaf(acc[i].z, acc[i].z, q.z); q.w = fmaf(acc[i].w, acc[i].w, q.w);
        }
    }
    #pragma unroll
    for (int o = 8; o <= 16; o <<= 1) {    // reduce across 4 rowgroups in warp
        s.x += __shfl_xor_sync(0xffffffffu, s.x, o); s.y += __shfl_xor_sync(0xffffffffu, s.y, o);
        s.z += __shfl_xor_sync(0xffffffffu, s.z, o); s.w += __shfl_xor_sync(0xffffffffu, s.w, o);
        q.x += __shfl_xor_sync(0xffffffffu, q.x, o); q.y += __shfl_xor_sync(0xffffffffu, q.y, o);
        q.z += __shfl_xor_sync(0xffffffffu, q.z, o); q.w += __shfl_xor_sync(0xffffffffu, q.w, o);
    }
    if ((tx & 31) < 8) {
        int w = tx >> 5;
        *(float4*)&red[w * 64 + cg * 4] = s;
        *(float4*)&red[w * 64 + 32 + cg * 4] = q;
    }
    __syncthreads();
    if (tx < 32) {
        float S = 0.f, Q = 0.f;
        #pragma unroll
        for (int w = 0; w < 8; w++) { S += red[w * 64 + tx]; Q += red[w * 64 + 32 + tx]; }
        atomicAdd(&g_sums[statoff + tx], S);
        atomicAdd(&g_sums[statoff + 32 + tx], Q);
    }
}

// ---------------- BN finalize ----------------------------------------------
__global__ void finalize_k(const float* __restrict__ gamma,
                           const float* __restrict__ beta,
                           int n, int off, int outoff) {
    int c = threadIdx.x;
    float inv_n = 1.f / (float)n;
    float mu  = g_sums[off + c] * inv_n;
    float var = g_sums[off + 32 + c] * inv_n - mu * mu;
    float sc  = gamma[c] * rsqrtf(var + BN_EPS);
    g_sums[outoff + c] = sc;
    g_sums[outoff + 32 + c] = beta[c] - mu * sc;
}

// ---------------- BN apply + ReLU ------------------------------------------
__global__ void apply_k(const float* __restrict__ in, float* __restrict__ out,
                        int n, int soff) {
    int total = n * 8;
    for (int i = blockIdx.x * blockDim.x + threadIdx.x; i < total;
         i += gridDim.x * blockDim.x) {
        int c4 = (i & 7) * 4;
        float4 v  = ((const float4*)in)[i];
        float4 sc = *(const float4*)&g_sums[soff + c4];
        float4 sh = *(const float4*)&g_sums[soff + 32 + c4];
        float4 o;
        o.x = fmaxf(fmaf(v.x, sc.x, sh.x), 0.f);
        o.y = fmaxf(fmaf(v.y, sc.y, sh.y), 0.f);
        o.z = fmaxf(fmaf(v.z, sc.z, sh.z), 0.f);
        o.w = fmaxf(fmaf(v.w, sc.w, sh.w), 0.f);
        ((float4*)out)[i] = o;
    }
}

// ---------------- launch ---------------------------------------------------
template <int CIN>
static int conv_smem_bytes() {
    int fl = 2 * 128 * (CIN + 4) + 2 * CIN * 32 + 512;
    int in = 256 + KOFF * 5 + 1;
    return (fl + in) * 4 + 16;
}

extern "C" void kernel_launch(void* const* d_in, const int* in_sizes, int n_in,
                              void* d_out, int out_size) {
    const float* feats  = (const float*)d_in[0];
    const float* W1     = (const float*)d_in[1];
    const float* gamma1 = (const float*)d_in[2];
    const float* beta1  = (const float*)d_in[3];
    const float* W2     = (const float*)d_in[4];
    const float* gamma2 = (const float*)d_in[5];
    const float* beta2  = (const float*)d_in[6];
    const int*   rin    = (const int*)d_in[7];
    const int*   rout   = (const int*)d_in[8];
    int n = in_sizes[0] / 16;

    float *acc1, *x1, *acc2;
    cudaGetSymbolAddress((void**)&acc1, g_acc1);
    cudaGetSymbolAddress((void**)&x1,   g_x1);
    cudaGetSymbolAddress((void**)&acc2, g_acc2);

    int smem1 = conv_smem_bytes<16>();
    int smem2 = conv_smem_bytes<32>();
    cudaFuncSetAttribute(conv_k<16>, cudaFuncAttributeMaxDynamicSharedMemorySize, smem1);
    cudaFuncSetAttribute(conv_k<32>, cudaFuncAttributeMaxDynamicSharedMemorySize, smem2);

    int tiles = (n + TILE - 1) / TILE;
    int segthreads = KOFF * (tiles + 1);

    seg_k<<<(segthreads + 255) / 256, 256>>>(rout, n, tiles);

    conv_k<16><<<tiles, 256, smem1>>>(feats, W1, rin, rout, acc1, n, 0);
    finalize_k<<<1, 32>>>(gamma1, beta1, n, 0, 128);
    apply_k<<<1184, 256>>>(acc1, x1, n, 128);

    conv_k<32><<<tiles, 256, smem2>>>(x1, W2, rin, rout, acc2, n, 64);
    finalize_k<<<1, 32>>>(gamma2, beta2, n, 64, 192);

    apply_k<<<1184, 256>>>(acc2, (float*)d_out, n, 192);
}